// round 10
// baseline (speedup 1.0000x reference)
#include <cuda_runtime.h>
#include <cuda.h>
#include <cuda_bf16.h>
#include <math.h>
#include <stdint.h>

#define Bb 256
#define Dd 2048
#define Nn 65536
#define Pp 4096
#define CTOT (Pp + Nn)
#define TINV 20.0f
#define EPS_ 0.1f

#define BNg 128                  // N cols per CTA
#define NBLK (Nn / BNg)          // 512 CTAs
#define KC 32                    // K elems per stage
#define NIT (Dd / KC)            // 64 stages
#define NSTG 4
#define A_BY 16384               // A bf16: 256 rows x 64 B (SW64)
#define BF_BY 16384              // B fp32: 128 rows x 128 B (SW128)
#define BB_BY 8192               // B bf16: 128 rows x 64 B (SW64-style)
#define STG_BY (A_BY + BF_BY + BB_BY)   // 40960
#define SMEM_DYN (NSTG * STG_BY + 1024)

__device__ __align__(128) float g_xn[Bb * Dd];
__device__ __align__(128) __nv_bfloat16 g_xnb[Bb * Dd];
__device__ float g_M[Bb], g_szp[Bb], g_sep[Bb], g_zt[Bb], g_rowloss[Bb];
__device__ float g_psv[Bb * NBLK], g_pse[Bb * NBLK];

// ---------------- PTX helpers ----------------
__device__ __forceinline__ uint32_t cvs(const void* p) {
    return (uint32_t)__cvta_generic_to_shared(p);
}
__device__ __forceinline__ void mbar_init(uint32_t a, uint32_t c) {
    asm volatile("mbarrier.init.shared.b64 [%0], %1;" :: "r"(a), "r"(c) : "memory");
}
__device__ __forceinline__ void mbar_expect(uint32_t a, uint32_t tx) {
    asm volatile("mbarrier.arrive.expect_tx.shared.b64 _, [%0], %1;"
                 :: "r"(a), "r"(tx) : "memory");
}
__device__ __forceinline__ void mbar_wait(uint32_t a, uint32_t ph) {
    asm volatile(
        "{\n\t.reg .pred P;\n\t"
        "W_%=:\n\t"
        "mbarrier.try_wait.parity.acquire.cta.shared::cta.b64 P, [%0], %1, 0x989680;\n\t"
        "@P bra D_%=;\n\t"
        "bra.uni W_%=;\n\t"
        "D_%=:\n\t}"
        :: "r"(a), "r"(ph) : "memory");
}
__device__ __forceinline__ void tma2d(uint32_t dst, const CUtensorMap* m,
                                      int x, int y, uint32_t bar) {
    asm volatile(
        "cp.async.bulk.tensor.2d.shared::cta.global.tile.mbarrier::complete_tx::bytes "
        "[%0], [%1, {%2, %3}], [%4];"
        :: "r"(dst), "l"(m), "r"(x), "r"(y), "r"(bar) : "memory");
}
__device__ __forceinline__ void ldsm4(uint32_t& r0, uint32_t& r1, uint32_t& r2,
                                      uint32_t& r3, uint32_t addr) {
    asm volatile(
        "ldmatrix.sync.aligned.m8n8.x4.shared.b16 {%0,%1,%2,%3}, [%4];"
        : "=r"(r0), "=r"(r1), "=r"(r2), "=r"(r3) : "r"(addr));
}
__device__ __forceinline__ void mma16(float c[4], const uint32_t a[4],
                                      uint32_t b0, uint32_t b1) {
    asm("mma.sync.aligned.m16n8k16.row.col.f32.bf16.bf16.f32 "
        "{%0,%1,%2,%3},{%4,%5,%6,%7},{%8,%9},{%0,%1,%2,%3};"
        : "+f"(c[0]), "+f"(c[1]), "+f"(c[2]), "+f"(c[3])
        : "r"(a[0]), "r"(a[1]), "r"(a[2]), "r"(a[3]), "r"(b0), "r"(b1));
}
__device__ __forceinline__ uint32_t pack2(float a, float b) {
    __nv_bfloat162 p = __floats2bfloat162_rn(a, b);
    return *(uint32_t*)&p;
}

// ---------------- K1: normalize inputs (fp32 + bf16 out) ----------------
__global__ void k_normalize(const float* __restrict__ in) {
    int row = blockIdx.x, tid = threadIdx.x;
    const float4* src = (const float4*)(in + (size_t)row * Dd);
    float4 v0 = src[tid], v1 = src[tid + 256];
    float ss = v0.x*v0.x + v0.y*v0.y + v0.z*v0.z + v0.w*v0.w
             + v1.x*v1.x + v1.y*v1.y + v1.z*v1.z + v1.w*v1.w;
    #pragma unroll
    for (int o = 16; o; o >>= 1) ss += __shfl_xor_sync(~0u, ss, o);
    __shared__ float sh[8];
    if ((tid & 31) == 0) sh[tid >> 5] = ss;
    __syncthreads();
    if (tid == 0) {
        float t = 0.f;
        #pragma unroll
        for (int i = 0; i < 8; i++) t += sh[i];
        sh[0] = rsqrtf(t);
    }
    __syncthreads();
    float iv = sh[0];
    v0.x*=iv; v0.y*=iv; v0.z*=iv; v0.w*=iv;
    v1.x*=iv; v1.y*=iv; v1.z*=iv; v1.w*=iv;
    float4* dst = (float4*)(g_xn + (size_t)row * Dd);
    dst[tid] = v0; dst[tid + 256] = v1;
    uint2* bdst = (uint2*)(g_xnb + (size_t)row * Dd);
    bdst[tid]       = make_uint2(pack2(v0.x, v0.y), pack2(v0.z, v0.w));
    bdst[tid + 256] = make_uint2(pack2(v1.x, v1.y), pack2(v1.z, v1.w));
}

// ---------------- K2: prototype stats ----------------
__global__ void k_prep(const float* __restrict__ proto) {
    int b = blockIdx.x, tid = threadIdx.x;
    const float4* pr = (const float4*)(proto + (size_t)b * Pp);
    float mx = -1e30f, sm = 0.f;
    #pragma unroll 4
    for (int i = tid; i < Pp / 4; i += 256) {
        float4 v = pr[i];
        sm += (v.x + v.y) + (v.z + v.w);
        mx = fmaxf(fmaxf(fmaxf(v.x, v.y), fmaxf(v.z, v.w)), mx);
    }
    __shared__ float rm[256], rs[256];
    rm[tid] = mx; rs[tid] = sm;
    __syncthreads();
    for (int o = 128; o; o >>= 1) {
        if (tid < o) { rm[tid] = fmaxf(rm[tid], rm[tid+o]); rs[tid] += rs[tid+o]; }
        __syncthreads();
    }
    float M = fmaxf(rm[0] * TINV, 21.f), S = rs[0] * TINV;
    __syncthreads();
    float se = 0.f;
    for (int i = tid; i < Pp / 4; i += 256) {
        float4 v = pr[i];
        if (fmaxf(fmaxf(v.x, v.y), fmaxf(v.z, v.w)) * TINV > M - 30.f) {
            se += __expf(v.x*TINV - M) + __expf(v.y*TINV - M)
                + __expf(v.z*TINV - M) + __expf(v.w*TINV - M);
        }
    }
    rs[tid] = se;
    __syncthreads();
    for (int o = 128; o; o >>= 1) {
        if (tid < o) rs[tid] += rs[tid+o];
        __syncthreads();
    }
    if (tid == 0) { g_M[b] = M; g_szp[b] = S; g_sep[b] = rs[0]; }
}

// ---------------- K3: exact fp32 target logit ----------------
__global__ void k_target(const float* __restrict__ F, const int* __restrict__ tg) {
    int b = blockIdx.x, tid = threadIdx.x;
    const float4* f = (const float4*)(F + (size_t)tg[b] * Dd);
    const float4* x = (const float4*)(g_xn + (size_t)b * Dd);
    float d = 0.f;
    for (int i = tid; i < Dd / 4; i += 256) {
        float4 a = x[i], c = f[i];
        d += a.x*c.x + a.y*c.y + a.z*c.z + a.w*c.w;
    }
    #pragma unroll
    for (int o = 16; o; o >>= 1) d += __shfl_xor_sync(~0u, d, o);
    __shared__ float sh[8];
    if ((tid & 31) == 0) sh[tid >> 5] = d;
    __syncthreads();
    if (tid == 0) {
        float t = 0.f;
        #pragma unroll
        for (int i = 0; i < 8; i++) t += sh[i];
        g_zt[b] = t * TINV;
    }
}

// ---------------- K4: 4-stage TMA + ldmatrix bf16 GEMM ----------
// CTA tile 256(M) x 128(N), stage k=32, 4 slots; 256 threads, 8 warps 4mx2n.
// A arrives bf16 (SW64, 64-B rows). B arrives fp32 (SW128), converted to a
// 64-B-row bf16 tile one stage ahead, overlapped with the tensor pipe.
__global__ void __launch_bounds__(256, 1) k_gemm(
    const __grid_constant__ CUtensorMap tmA,
    const __grid_constant__ CUtensorMap tmB) {
    extern __shared__ char dsm[];
    __shared__ __align__(8) uint64_t s_bar[NSTG];   // full[0..3]

    int tid = threadIdx.x, lane = tid & 31, wid = tid >> 5;
    int wm = wid >> 1, wn = wid & 1;
    int n0 = blockIdx.x * BNg;
    uint32_t sb = (cvs(dsm) + 1023u) & ~1023u;
    uint32_t fullb = cvs(s_bar);

    if (tid == 0) {
        #pragma unroll
        for (int i = 0; i < NSTG; i++) mbar_init(fullb + 8*i, 1);
    }
    __syncthreads();
    if (tid == 0) {
        #pragma unroll
        for (int p = 0; p < NSTG; p++) {
            mbar_expect(fullb + 8*p, A_BY + BF_BY);
            tma2d(sb + p*STG_BY,        &tmA, p*KC, 0,  fullb + 8*p);
            tma2d(sb + p*STG_BY + A_BY, &tmB, p*KC, n0, fullb + 8*p);
        }
    }

    // ---- conversion geometry: 2 threads per B row, 16 floats each ----
    int cn = tid >> 1, cc = tid & 1;
    uint32_t Xc  = (uint32_t)(cn & 7) << 4;          // SW128 (fp32 src)
    uint32_t Xc6 = (uint32_t)((cn >> 1) & 3) << 4;   // SW64 (bf16 dst)
    uint32_t csrc = (uint32_t)(A_BY + cn * 128);
    uint32_t cdst = (uint32_t)(A_BY + BF_BY + cn * 64);
    uint32_t cso  = (uint32_t)cc * 64u;
    uint32_t cdo  = (uint32_t)cc * 32u;

    // ---- ldmatrix lane geometry (64-B rows, SW64: X=((r>>1)&3)<<4) ----
    int l15 = lane & 15;
    uint32_t aHi = (uint32_t)(lane >> 4) << 4;
    uint32_t rowAddrA[4], Xa[4];
    #pragma unroll
    for (int mt = 0; mt < 4; mt++) {
        int row = wm*64 + mt*16 + l15;
        rowAddrA[mt] = (uint32_t)row * 64u;
        Xa[mt] = (uint32_t)((row >> 1) & 3) << 4;
    }
    int j = lane >> 3;
    uint32_t bCol = (uint32_t)(j & 1) << 4;
    uint32_t rowAddrB[4], Xb[4];
    #pragma unroll
    for (int u = 0; u < 4; u++) {
        int row = wn*64 + u*16 + (lane & 7) + (j >> 1) * 8;
        rowAddrB[u] = (uint32_t)(A_BY + BF_BY) + (uint32_t)row * 64u;
        Xb[u] = (uint32_t)((row >> 1) & 3) << 4;
    }

    float c[4][8][4];
    #pragma unroll
    for (int i = 0; i < 4; i++)
        #pragma unroll
        for (int jj = 0; jj < 8; jj++)
            #pragma unroll
            for (int k = 0; k < 4; k++) c[i][jj][k] = 0.f;

    // ---- prologue: wait stage 0, convert its B, sync ----
    mbar_wait(fullb + 0, 0);
    {
        uint32_t srcb = sb + csrc;
        uint32_t dstb = sb + cdst;
        float4 f0, f1, f2, f3;
        asm volatile("ld.shared.v4.f32 {%0,%1,%2,%3}, [%4];"
            : "=f"(f0.x), "=f"(f0.y), "=f"(f0.z), "=f"(f0.w)
            : "r"(srcb + ((cso +  0u) ^ Xc)));
        asm volatile("ld.shared.v4.f32 {%0,%1,%2,%3}, [%4];"
            : "=f"(f1.x), "=f"(f1.y), "=f"(f1.z), "=f"(f1.w)
            : "r"(srcb + ((cso + 16u) ^ Xc)));
        asm volatile("ld.shared.v4.f32 {%0,%1,%2,%3}, [%4];"
            : "=f"(f2.x), "=f"(f2.y), "=f"(f2.z), "=f"(f2.w)
            : "r"(srcb + ((cso + 32u) ^ Xc)));
        asm volatile("ld.shared.v4.f32 {%0,%1,%2,%3}, [%4];"
            : "=f"(f3.x), "=f"(f3.y), "=f"(f3.z), "=f"(f3.w)
            : "r"(srcb + ((cso + 48u) ^ Xc)));
        asm volatile("st.shared.v4.b32 [%0], {%1,%2,%3,%4};"
            :: "r"(dstb + ((cdo +  0u) ^ Xc6)),
               "r"(pack2(f0.x, f0.y)), "r"(pack2(f0.z, f0.w)),
               "r"(pack2(f1.x, f1.y)), "r"(pack2(f1.z, f1.w)) : "memory");
        asm volatile("st.shared.v4.b32 [%0], {%1,%2,%3,%4};"
            :: "r"(dstb + ((cdo + 16u) ^ Xc6)),
               "r"(pack2(f2.x, f2.y)), "r"(pack2(f2.z, f2.w)),
               "r"(pack2(f3.x, f3.y)), "r"(pack2(f3.z, f3.w)) : "memory");
    }
    __syncthreads();

    for (int it = 0; it < NIT; it++) {
        int s = it & 3;
        uint32_t sbase = sb + s * STG_BY;

        // ---- 1) issue compute for stage it (fills the tensor queue) ----
        #pragma unroll
        for (int s4 = 0; s4 < 2; s4++) {
            uint32_t kb = (uint32_t)s4 * 32u;
            uint32_t a[4][4], bfr[4][4];
            #pragma unroll
            for (int mt = 0; mt < 4; mt++)
                ldsm4(a[mt][0], a[mt][1], a[mt][2], a[mt][3],
                      sbase + rowAddrA[mt] + ((kb + aHi) ^ Xa[mt]));
            #pragma unroll
            for (int u = 0; u < 4; u++)
                ldsm4(bfr[u][0], bfr[u][1], bfr[u][2], bfr[u][3],
                      sbase + rowAddrB[u] + ((kb + bCol) ^ Xb[u]));
            #pragma unroll
            for (int mt = 0; mt < 4; mt++)
                #pragma unroll
                for (int u = 0; u < 4; u++) {
                    mma16(c[mt][2*u],     a[mt], bfr[u][0], bfr[u][1]);
                    mma16(c[mt][2*u + 1], a[mt], bfr[u][2], bfr[u][3]);
                }
        }

        // ---- 2) overlap: wait TMA of stage it+1, convert its B ----
        if (it + 1 < NIT) {
            int nx = (it + 1) & 3;
            mbar_wait(fullb + 8*nx, (uint32_t)(((it + 1) >> 2) & 1));
            uint32_t srcb = sb + nx * STG_BY + csrc;
            uint32_t dstb = sb + nx * STG_BY + cdst;
            float4 f0, f1, f2, f3;
            asm volatile("ld.shared.v4.f32 {%0,%1,%2,%3}, [%4];"
                : "=f"(f0.x), "=f"(f0.y), "=f"(f0.z), "=f"(f0.w)
                : "r"(srcb + ((cso +  0u) ^ Xc)));
            asm volatile("ld.shared.v4.f32 {%0,%1,%2,%3}, [%4];"
                : "=f"(f1.x), "=f"(f1.y), "=f"(f1.z), "=f"(f1.w)
                : "r"(srcb + ((cso + 16u) ^ Xc)));
            asm volatile("ld.shared.v4.f32 {%0,%1,%2,%3}, [%4];"
                : "=f"(f2.x), "=f"(f2.y), "=f"(f2.z), "=f"(f2.w)
                : "r"(srcb + ((cso + 32u) ^ Xc)));
            asm volatile("ld.shared.v4.f32 {%0,%1,%2,%3}, [%4];"
                : "=f"(f3.x), "=f"(f3.y), "=f"(f3.z), "=f"(f3.w)
                : "r"(srcb + ((cso + 48u) ^ Xc)));
            asm volatile("st.shared.v4.b32 [%0], {%1,%2,%3,%4};"
                :: "r"(dstb + ((cdo +  0u) ^ Xc6)),
                   "r"(pack2(f0.x, f0.y)), "r"(pack2(f0.z, f0.w)),
                   "r"(pack2(f1.x, f1.y)), "r"(pack2(f1.z, f1.w)) : "memory");
            asm volatile("st.shared.v4.b32 [%0], {%1,%2,%3,%4};"
                :: "r"(dstb + ((cdo + 16u) ^ Xc6)),
                   "r"(pack2(f2.x, f2.y)), "r"(pack2(f2.z, f2.w)),
                   "r"(pack2(f3.x, f3.y)), "r"(pack2(f3.z, f3.w)) : "memory");
        }

        // ---- 3) single barrier: compute(s) reads + convert(nx) writes ----
        __syncthreads();

        // ---- 4) refill slot s with stage it+4 ----
        if (tid == 0 && it + 4 < NIT) {
            int k0 = (it + 4) * KC;
            mbar_expect(fullb + 8*s, A_BY + BF_BY);
            tma2d(sbase,        &tmA, k0, 0,  fullb + 8*s);
            tma2d(sbase + A_BY, &tmB, k0, n0, fullb + 8*s);
        }
    }
    __syncthreads();

    // ---- fused epilogue: per-row sum + softmax numerator partials ----
    int g = lane >> 2, q = lane & 3;
    float* redv = (float*)dsm;          // [2 wn][256 rows]
    float* rede = redv + 512;
    #pragma unroll
    for (int mt = 0; mt < 4; mt++) {
        int r0 = wm*64 + mt*16 + g;
        float M0 = g_M[r0], M1 = g_M[r0 + 8];
        float sv0 = 0.f, se0 = 0.f, sv1 = 0.f, se1 = 0.f;
        #pragma unroll
        for (int nt = 0; nt < 8; nt++) {
            float v;
            v = c[mt][nt][0]; sv0 += v; se0 += __expf(fmaf(TINV, v, -M0));
            v = c[mt][nt][1]; sv0 += v; se0 += __expf(fmaf(TINV, v, -M0));
            v = c[mt][nt][2]; sv1 += v; se1 += __expf(fmaf(TINV, v, -M1));
            v = c[mt][nt][3]; sv1 += v; se1 += __expf(fmaf(TINV, v, -M1));
        }
        #pragma unroll
        for (int o = 1; o <= 2; o <<= 1) {
            sv0 += __shfl_xor_sync(~0u, sv0, o);
            se0 += __shfl_xor_sync(~0u, se0, o);
            sv1 += __shfl_xor_sync(~0u, sv1, o);
            se1 += __shfl_xor_sync(~0u, se1, o);
        }
        if (q == 0) {
            redv[wn*256 + r0]     = sv0; rede[wn*256 + r0]     = se0;
            redv[wn*256 + r0 + 8] = sv1; rede[wn*256 + r0 + 8] = se1;
        }
    }
    __syncthreads();
    {
        float sv = redv[tid] + redv[256 + tid];
        float se = rede[tid] + rede[256 + tid];
        g_psv[(size_t)tid * NBLK + blockIdx.x] = sv;
        g_pse[(size_t)tid * NBLK + blockIdx.x] = se;
    }
}

// ---------------- K5: per-row combine over 512 CTA partials ----------------
__global__ void k_finalrow(void) {
    int b = blockIdx.x, tid = threadIdx.x;
    float sv = g_psv[(size_t)b * NBLK + tid] + g_psv[(size_t)b * NBLK + tid + 256];
    float se = g_pse[(size_t)b * NBLK + tid] + g_pse[(size_t)b * NBLK + tid + 256];
    __shared__ float rv[256], re[256];
    rv[tid] = sv; re[tid] = se;
    __syncthreads();
    for (int o = 128; o; o >>= 1) {
        if (tid < o) { rv[tid] += rv[tid+o]; re[tid] += re[tid+o]; }
        __syncthreads();
    }
    if (tid == 0) {
        float M = g_M[b];
        float lse = M + logf(g_sep[b] + re[0]);
        float T = g_szp[b] + TINV * rv[0];
        g_rowloss[b] = lse - (1.f - EPS_) * g_zt[b] - EPS_ * (T / (float)CTOT);
    }
}

// ---------------- K6: mean ----------------
__global__ void k_final(float* __restrict__ out) {
    int tid = threadIdx.x;
    float v = g_rowloss[tid];
    #pragma unroll
    for (int o = 16; o; o >>= 1) v += __shfl_xor_sync(~0u, v, o);
    __shared__ float sh[8];
    if ((tid & 31) == 0) sh[tid >> 5] = v;
    __syncthreads();
    if (tid == 0) {
        float s = 0.f;
        #pragma unroll
        for (int i = 0; i < 8; i++) s += sh[i];
        out[0] = s / (float)Bb;
    }
}

// ---------------------------------------------------------------------------
typedef CUresult (*PFN_tmapenc)(
    CUtensorMap*, CUtensorMapDataType, cuuint32_t, void*,
    const cuuint64_t*, const cuuint64_t*, const cuuint32_t*, const cuuint32_t*,
    CUtensorMapInterleave, CUtensorMapSwizzle, CUtensorMapL2promotion,
    CUtensorMapFloatOOBfill);

extern "C" void kernel_launch(void* const* d_in, const int* in_sizes, int n_in,
                              void* d_out, int out_size) {
    const float* inputs    = (const float*)d_in[0];
    const int*   targets   = (const int*)  d_in[1];
    const float* prototype = (const float*)d_in[2];
    const float* features  = (const float*)d_in[3];
    float* out = (float*)d_out;

    cudaFuncSetAttribute(k_gemm, cudaFuncAttributeMaxDynamicSharedMemorySize,
                         SMEM_DYN);

    PFN_tmapenc enc = nullptr;
    cudaDriverEntryPointQueryResult qr;
    cudaGetDriverEntryPointByVersion("cuTensorMapEncodeTiled", (void**)&enc,
                                     12000, cudaEnableDefault, &qr);

    void* xnbp = nullptr;
    cudaGetSymbolAddress(&xnbp, g_xnb);

    CUtensorMap tmA, tmB;
    {
        cuuint64_t dims[2]    = {Dd, Bb};
        cuuint64_t strides[1] = {Dd * 2ull};
        cuuint32_t box[2]     = {KC, Bb};          // 32 bf16 = 64 B x 256 rows
        cuuint32_t es[2]      = {1, 1};
        enc(&tmA, CU_TENSOR_MAP_DATA_TYPE_BFLOAT16, 2, xnbp, dims, strides, box, es,
            CU_TENSOR_MAP_INTERLEAVE_NONE, CU_TENSOR_MAP_SWIZZLE_64B,
            CU_TENSOR_MAP_L2_PROMOTION_L2_128B, CU_TENSOR_MAP_FLOAT_OOB_FILL_NONE);
    }
    {
        cuuint64_t dims[2]    = {Dd, Nn};
        cuuint64_t strides[1] = {Dd * 4ull};
        cuuint32_t box[2]     = {KC, BNg};         // 32 f32 = 128 B x 128 rows
        cuuint32_t es[2]      = {1, 1};
        enc(&tmB, CU_TENSOR_MAP_DATA_TYPE_FLOAT32, 2, (void*)features,
            dims, strides, box, es,
            CU_TENSOR_MAP_INTERLEAVE_NONE, CU_TENSOR_MAP_SWIZZLE_128B,
            CU_TENSOR_MAP_L2_PROMOTION_L2_128B, CU_TENSOR_MAP_FLOAT_OOB_FILL_NONE);
    }

    k_normalize<<<Bb, 256>>>(inputs);
    k_prep<<<Bb, 256>>>(prototype);
    k_target<<<Bb, 256>>>(features, targets);
    k_gemm<<<NBLK, 256, SMEM_DYN>>>(tmA, tmB);
    k_finalrow<<<Bb, 256>>>();
    k_final<<<1, 256>>>(out);
}

// round 11
// speedup vs baseline: 1.0195x; 1.0195x over previous
#include <cuda_runtime.h>
#include <cuda.h>
#include <cuda_bf16.h>
#include <math.h>
#include <stdint.h>

#define Bb 256
#define Dd 2048
#define Nn 65536
#define Pp 4096
#define CTOT (Pp + Nn)
#define TINV 20.0f
#define EPS_ 0.1f

#define BNg 128                  // N cols per CTA
#define NBLK (Nn / BNg)          // 512 CTAs
#define KC 32                    // K elems per stage
#define NIT (Dd / KC)            // 64 stages
#define NSTG 4
#define A_BY 16384               // A bf16: 256 rows x 64 B (SW64)
#define BF_BY 16384              // B fp32: 128 rows x 128 B (SW128)
#define BB_BY 8192               // B bf16: 128 rows x 64 B (SW64-style)
#define STG_BY (A_BY + BF_BY + BB_BY)   // 40960
#define SMEM_DYN (NSTG * STG_BY + 1024)

__device__ __align__(128) float g_xn[Bb * Dd];
__device__ __align__(128) __nv_bfloat16 g_xnb[Bb * Dd];
__device__ float g_M[Bb], g_szp[Bb], g_sep[Bb], g_zt[Bb], g_rowloss[Bb];
__device__ float g_psv[Bb * NBLK], g_pse[Bb * NBLK];

// ---------------- PTX helpers ----------------
__device__ __forceinline__ uint32_t cvs(const void* p) {
    return (uint32_t)__cvta_generic_to_shared(p);
}
__device__ __forceinline__ void mbar_init(uint32_t a, uint32_t c) {
    asm volatile("mbarrier.init.shared.b64 [%0], %1;" :: "r"(a), "r"(c) : "memory");
}
__device__ __forceinline__ void mbar_expect(uint32_t a, uint32_t tx) {
    asm volatile("mbarrier.arrive.expect_tx.shared.b64 _, [%0], %1;"
                 :: "r"(a), "r"(tx) : "memory");
}
__device__ __forceinline__ void mbar_wait(uint32_t a, uint32_t ph) {
    asm volatile(
        "{\n\t.reg .pred P;\n\t"
        "W_%=:\n\t"
        "mbarrier.try_wait.parity.acquire.cta.shared::cta.b64 P, [%0], %1, 0x989680;\n\t"
        "@P bra D_%=;\n\t"
        "bra.uni W_%=;\n\t"
        "D_%=:\n\t}"
        :: "r"(a), "r"(ph) : "memory");
}
__device__ __forceinline__ void tma2d(uint32_t dst, const CUtensorMap* m,
                                      int x, int y, uint32_t bar) {
    asm volatile(
        "cp.async.bulk.tensor.2d.shared::cta.global.tile.mbarrier::complete_tx::bytes "
        "[%0], [%1, {%2, %3}], [%4];"
        :: "r"(dst), "l"(m), "r"(x), "r"(y), "r"(bar) : "memory");
}
__device__ __forceinline__ void ldsm4(uint32_t& r0, uint32_t& r1, uint32_t& r2,
                                      uint32_t& r3, uint32_t addr) {
    asm volatile(
        "ldmatrix.sync.aligned.m8n8.x4.shared.b16 {%0,%1,%2,%3}, [%4];"
        : "=r"(r0), "=r"(r1), "=r"(r2), "=r"(r3) : "r"(addr));
}
__device__ __forceinline__ void mma16(float c[4], const uint32_t a[4],
                                      uint32_t b0, uint32_t b1) {
    asm("mma.sync.aligned.m16n8k16.row.col.f32.bf16.bf16.f32 "
        "{%0,%1,%2,%3},{%4,%5,%6,%7},{%8,%9},{%0,%1,%2,%3};"
        : "+f"(c[0]), "+f"(c[1]), "+f"(c[2]), "+f"(c[3])
        : "r"(a[0]), "r"(a[1]), "r"(a[2]), "r"(a[3]), "r"(b0), "r"(b1));
}
__device__ __forceinline__ uint32_t pack2(float a, float b) {
    __nv_bfloat162 p = __floats2bfloat162_rn(a, b);
    return *(uint32_t*)&p;
}

// ---------------- K1: normalize inputs (fp32 + bf16 out) ----------------
__global__ void k_normalize(const float* __restrict__ in) {
    int row = blockIdx.x, tid = threadIdx.x;
    const float4* src = (const float4*)(in + (size_t)row * Dd);
    float4 v0 = src[tid], v1 = src[tid + 256];
    float ss = v0.x*v0.x + v0.y*v0.y + v0.z*v0.z + v0.w*v0.w
             + v1.x*v1.x + v1.y*v1.y + v1.z*v1.z + v1.w*v1.w;
    #pragma unroll
    for (int o = 16; o; o >>= 1) ss += __shfl_xor_sync(~0u, ss, o);
    __shared__ float sh[8];
    if ((tid & 31) == 0) sh[tid >> 5] = ss;
    __syncthreads();
    if (tid == 0) {
        float t = 0.f;
        #pragma unroll
        for (int i = 0; i < 8; i++) t += sh[i];
        sh[0] = rsqrtf(t);
    }
    __syncthreads();
    float iv = sh[0];
    v0.x*=iv; v0.y*=iv; v0.z*=iv; v0.w*=iv;
    v1.x*=iv; v1.y*=iv; v1.z*=iv; v1.w*=iv;
    float4* dst = (float4*)(g_xn + (size_t)row * Dd);
    dst[tid] = v0; dst[tid + 256] = v1;
    uint2* bdst = (uint2*)(g_xnb + (size_t)row * Dd);
    bdst[tid]       = make_uint2(pack2(v0.x, v0.y), pack2(v0.z, v0.w));
    bdst[tid + 256] = make_uint2(pack2(v1.x, v1.y), pack2(v1.z, v1.w));
}

// ---------------- K2: prototype stats ----------------
__global__ void k_prep(const float* __restrict__ proto) {
    int b = blockIdx.x, tid = threadIdx.x;
    const float4* pr = (const float4*)(proto + (size_t)b * Pp);
    float mx = -1e30f, sm = 0.f;
    #pragma unroll 4
    for (int i = tid; i < Pp / 4; i += 256) {
        float4 v = pr[i];
        sm += (v.x + v.y) + (v.z + v.w);
        mx = fmaxf(fmaxf(fmaxf(v.x, v.y), fmaxf(v.z, v.w)), mx);
    }
    __shared__ float rm[256], rs[256];
    rm[tid] = mx; rs[tid] = sm;
    __syncthreads();
    for (int o = 128; o; o >>= 1) {
        if (tid < o) { rm[tid] = fmaxf(rm[tid], rm[tid+o]); rs[tid] += rs[tid+o]; }
        __syncthreads();
    }
    float M = fmaxf(rm[0] * TINV, 21.f), S = rs[0] * TINV;
    __syncthreads();
    float se = 0.f;
    for (int i = tid; i < Pp / 4; i += 256) {
        float4 v = pr[i];
        if (fmaxf(fmaxf(v.x, v.y), fmaxf(v.z, v.w)) * TINV > M - 30.f) {
            se += __expf(v.x*TINV - M) + __expf(v.y*TINV - M)
                + __expf(v.z*TINV - M) + __expf(v.w*TINV - M);
        }
    }
    rs[tid] = se;
    __syncthreads();
    for (int o = 128; o; o >>= 1) {
        if (tid < o) rs[tid] += rs[tid+o];
        __syncthreads();
    }
    if (tid == 0) { g_M[b] = M; g_szp[b] = S; g_sep[b] = rs[0]; }
}

// ---------------- K3: exact fp32 target logit ----------------
__global__ void k_target(const float* __restrict__ F, const int* __restrict__ tg) {
    int b = blockIdx.x, tid = threadIdx.x;
    const float4* f = (const float4*)(F + (size_t)tg[b] * Dd);
    const float4* x = (const float4*)(g_xn + (size_t)b * Dd);
    float d = 0.f;
    for (int i = tid; i < Dd / 4; i += 256) {
        float4 a = x[i], c = f[i];
        d += a.x*c.x + a.y*c.y + a.z*c.z + a.w*c.w;
    }
    #pragma unroll
    for (int o = 16; o; o >>= 1) d += __shfl_xor_sync(~0u, d, o);
    __shared__ float sh[8];
    if ((tid & 31) == 0) sh[tid >> 5] = d;
    __syncthreads();
    if (tid == 0) {
        float t = 0.f;
        #pragma unroll
        for (int i = 0; i < 8; i++) t += sh[i];
        g_zt[b] = t * TINV;
    }
}

// ---------------- K4: 4-stage TMA + ldmatrix bf16 GEMM, staggered warps ----
// CTA tile 256(M) x 128(N), stage k=32, 4 slots; 256 threads, 8 warps 4mx2n.
// Warps 0-3 (group X): compute(it) then convert(it+1).
// Warps 4-7 (group Y): convert(it+1) then compute(it).
// Each SMSP hosts one X and one Y warp -> tensor pipe stays fed while the
// other group's convert runs in the spare issue slots.
__global__ void __launch_bounds__(256, 1) k_gemm(
    const __grid_constant__ CUtensorMap tmA,
    const __grid_constant__ CUtensorMap tmB) {
    extern __shared__ char dsm[];
    __shared__ __align__(8) uint64_t s_bar[NSTG];   // full[0..3]

    int tid = threadIdx.x, lane = tid & 31, wid = tid >> 5;
    int wm = wid >> 1, wn = wid & 1;
    int n0 = blockIdx.x * BNg;
    uint32_t sb = (cvs(dsm) + 1023u) & ~1023u;
    uint32_t fullb = cvs(s_bar);
    bool early = (wid & 4) != 0;     // group Y: convert first

    if (tid == 0) {
        #pragma unroll
        for (int i = 0; i < NSTG; i++) mbar_init(fullb + 8*i, 1);
    }
    __syncthreads();
    if (tid == 0) {
        #pragma unroll
        for (int p = 0; p < NSTG; p++) {
            mbar_expect(fullb + 8*p, A_BY + BF_BY);
            tma2d(sb + p*STG_BY,        &tmA, p*KC, 0,  fullb + 8*p);
            tma2d(sb + p*STG_BY + A_BY, &tmB, p*KC, n0, fullb + 8*p);
        }
    }

    // ---- conversion geometry: 2 threads per B row, 16 floats each ----
    int cn = tid >> 1, cc = tid & 1;
    uint32_t Xc  = (uint32_t)(cn & 7) << 4;          // SW128 (fp32 src)
    uint32_t Xc6 = (uint32_t)((cn >> 1) & 3) << 4;   // SW64 (bf16 dst)
    uint32_t csrc = (uint32_t)(A_BY + cn * 128);
    uint32_t cdst = (uint32_t)(A_BY + BF_BY + cn * 64);
    uint32_t cso  = (uint32_t)cc * 64u;
    uint32_t cdo  = (uint32_t)cc * 32u;

    // ---- ldmatrix lane geometry (64-B rows, SW64: X=((r>>1)&3)<<4) ----
    int l15 = lane & 15;
    uint32_t aHi = (uint32_t)(lane >> 4) << 4;
    uint32_t rowAddrA[4], Xa[4];
    #pragma unroll
    for (int mt = 0; mt < 4; mt++) {
        int row = wm*64 + mt*16 + l15;
        rowAddrA[mt] = (uint32_t)row * 64u;
        Xa[mt] = (uint32_t)((row >> 1) & 3) << 4;
    }
    int j = lane >> 3;
    uint32_t bCol = (uint32_t)(j & 1) << 4;
    uint32_t rowAddrB[4], Xb[4];
    #pragma unroll
    for (int u = 0; u < 4; u++) {
        int row = wn*64 + u*16 + (lane & 7) + (j >> 1) * 8;
        rowAddrB[u] = (uint32_t)(A_BY + BF_BY) + (uint32_t)row * 64u;
        Xb[u] = (uint32_t)((row >> 1) & 3) << 4;
    }

    float c[4][8][4];
    #pragma unroll
    for (int i = 0; i < 4; i++)
        #pragma unroll
        for (int jj = 0; jj < 8; jj++)
            #pragma unroll
            for (int k = 0; k < 4; k++) c[i][jj][k] = 0.f;

    // convert stage stg's B fp32 -> bf16 (this thread's 16 floats)
    auto do_convert = [&](int stg) {
        uint32_t base = sb + (uint32_t)(stg & 3) * STG_BY;
        uint32_t srcb = base + csrc;
        uint32_t dstb = base + cdst;
        float4 f0, f1, f2, f3;
        asm volatile("ld.shared.v4.f32 {%0,%1,%2,%3}, [%4];"
            : "=f"(f0.x), "=f"(f0.y), "=f"(f0.z), "=f"(f0.w)
            : "r"(srcb + ((cso +  0u) ^ Xc)));
        asm volatile("ld.shared.v4.f32 {%0,%1,%2,%3}, [%4];"
            : "=f"(f1.x), "=f"(f1.y), "=f"(f1.z), "=f"(f1.w)
            : "r"(srcb + ((cso + 16u) ^ Xc)));
        asm volatile("ld.shared.v4.f32 {%0,%1,%2,%3}, [%4];"
            : "=f"(f2.x), "=f"(f2.y), "=f"(f2.z), "=f"(f2.w)
            : "r"(srcb + ((cso + 32u) ^ Xc)));
        asm volatile("ld.shared.v4.f32 {%0,%1,%2,%3}, [%4];"
            : "=f"(f3.x), "=f"(f3.y), "=f"(f3.z), "=f"(f3.w)
            : "r"(srcb + ((cso + 48u) ^ Xc)));
        asm volatile("st.shared.v4.b32 [%0], {%1,%2,%3,%4};"
            :: "r"(dstb + ((cdo +  0u) ^ Xc6)),
               "r"(pack2(f0.x, f0.y)), "r"(pack2(f0.z, f0.w)),
               "r"(pack2(f1.x, f1.y)), "r"(pack2(f1.z, f1.w)) : "memory");
        asm volatile("st.shared.v4.b32 [%0], {%1,%2,%3,%4};"
            :: "r"(dstb + ((cdo + 16u) ^ Xc6)),
               "r"(pack2(f2.x, f2.y)), "r"(pack2(f2.z, f2.w)),
               "r"(pack2(f3.x, f3.y)), "r"(pack2(f3.z, f3.w)) : "memory");
    };

    // compute stage resident in slot sbase
    auto do_compute = [&](uint32_t sbase) {
        #pragma unroll
        for (int s4 = 0; s4 < 2; s4++) {
            uint32_t kb = (uint32_t)s4 * 32u;
            uint32_t a[4][4], bfr[4][4];
            #pragma unroll
            for (int mt = 0; mt < 4; mt++)
                ldsm4(a[mt][0], a[mt][1], a[mt][2], a[mt][3],
                      sbase + rowAddrA[mt] + ((kb + aHi) ^ Xa[mt]));
            #pragma unroll
            for (int u = 0; u < 4; u++)
                ldsm4(bfr[u][0], bfr[u][1], bfr[u][2], bfr[u][3],
                      sbase + rowAddrB[u] + ((kb + bCol) ^ Xb[u]));
            #pragma unroll
            for (int mt = 0; mt < 4; mt++)
                #pragma unroll
                for (int u = 0; u < 4; u++) {
                    mma16(c[mt][2*u],     a[mt], bfr[u][0], bfr[u][1]);
                    mma16(c[mt][2*u + 1], a[mt], bfr[u][2], bfr[u][3]);
                }
        }
    };

    // ---- prologue: wait stage 0, all warps convert it, sync ----
    mbar_wait(fullb + 0, 0);
    do_convert(0);
    __syncthreads();

    for (int it = 0; it < NIT; it++) {
        int s = it & 3;
        uint32_t sbase = sb + (uint32_t)s * STG_BY;

        if (early) {
            if (it + 1 < NIT) {
                mbar_wait(fullb + 8*((it + 1) & 3), (uint32_t)(((it + 1) >> 2) & 1));
                do_convert(it + 1);
            }
            do_compute(sbase);
        } else {
            do_compute(sbase);
            if (it + 1 < NIT) {
                mbar_wait(fullb + 8*((it + 1) & 3), (uint32_t)(((it + 1) >> 2) & 1));
                do_convert(it + 1);
            }
        }

        // single barrier: compute(s) reads done + convert(it+1) writes visible
        __syncthreads();

        // refill slot s with stage it+4
        if (tid == 0 && it + 4 < NIT) {
            int k0 = (it + 4) * KC;
            mbar_expect(fullb + 8*s, A_BY + BF_BY);
            tma2d(sbase,        &tmA, k0, 0,  fullb + 8*s);
            tma2d(sbase + A_BY, &tmB, k0, n0, fullb + 8*s);
        }
    }
    __syncthreads();

    // ---- fused epilogue: per-row sum + softmax numerator partials ----
    int g = lane >> 2, q = lane & 3;
    float* redv = (float*)dsm;          // [2 wn][256 rows]
    float* rede = redv + 512;
    #pragma unroll
    for (int mt = 0; mt < 4; mt++) {
        int r0 = wm*64 + mt*16 + g;
        float M0 = g_M[r0], M1 = g_M[r0 + 8];
        float sv0 = 0.f, se0 = 0.f, sv1 = 0.f, se1 = 0.f;
        #pragma unroll
        for (int nt = 0; nt < 8; nt++) {
            float v;
            v = c[mt][nt][0]; sv0 += v; se0 += __expf(fmaf(TINV, v, -M0));
            v = c[mt][nt][1]; sv0 += v; se0 += __expf(fmaf(TINV, v, -M0));
            v = c[mt][nt][2]; sv1 += v; se1 += __expf(fmaf(TINV, v, -M1));
            v = c[mt][nt][3]; sv1 += v; se1 += __expf(fmaf(TINV, v, -M1));
        }
        #pragma unroll
        for (int o = 1; o <= 2; o <<= 1) {
            sv0 += __shfl_xor_sync(~0u, sv0, o);
            se0 += __shfl_xor_sync(~0u, se0, o);
            sv1 += __shfl_xor_sync(~0u, sv1, o);
            se1 += __shfl_xor_sync(~0u, se1, o);
        }
        if (q == 0) {
            redv[wn*256 + r0]     = sv0; rede[wn*256 + r0]     = se0;
            redv[wn*256 + r0 + 8] = sv1; rede[wn*256 + r0 + 8] = se1;
        }
    }
    __syncthreads();
    {
        float sv = redv[tid] + redv[256 + tid];
        float se = rede[tid] + rede[256 + tid];
        g_psv[(size_t)tid * NBLK + blockIdx.x] = sv;
        g_pse[(size_t)tid * NBLK + blockIdx.x] = se;
    }
}

// ---------------- K5: per-row combine over 512 CTA partials ----------------
__global__ void k_finalrow(void) {
    int b = blockIdx.x, tid = threadIdx.x;
    float sv = g_psv[(size_t)b * NBLK + tid] + g_psv[(size_t)b * NBLK + tid + 256];
    float se = g_pse[(size_t)b * NBLK + tid] + g_pse[(size_t)b * NBLK + tid + 256];
    __shared__ float rv[256], re[256];
    rv[tid] = sv; re[tid] = se;
    __syncthreads();
    for (int o = 128; o; o >>= 1) {
        if (tid < o) { rv[tid] += rv[tid+o]; re[tid] += re[tid+o]; }
        __syncthreads();
    }
    if (tid == 0) {
        float M = g_M[b];
        float lse = M + logf(g_sep[b] + re[0]);
        float T = g_szp[b] + TINV * rv[0];
        g_rowloss[b] = lse - (1.f - EPS_) * g_zt[b] - EPS_ * (T / (float)CTOT);
    }
}

// ---------------- K6: mean ----------------
__global__ void k_final(float* __restrict__ out) {
    int tid = threadIdx.x;
    float v = g_rowloss[tid];
    #pragma unroll
    for (int o = 16; o; o >>= 1) v += __shfl_xor_sync(~0u, v, o);
    __shared__ float sh[8];
    if ((tid & 31) == 0) sh[tid >> 5] = v;
    __syncthreads();
    if (tid == 0) {
        float s = 0.f;
        #pragma unroll
        for (int i = 0; i < 8; i++) s += sh[i];
        out[0] = s / (float)Bb;
    }
}

// ---------------------------------------------------------------------------
typedef CUresult (*PFN_tmapenc)(
    CUtensorMap*, CUtensorMapDataType, cuuint32_t, void*,
    const cuuint64_t*, const cuuint64_t*, const cuuint32_t*, const cuuint32_t*,
    CUtensorMapInterleave, CUtensorMapSwizzle, CUtensorMapL2promotion,
    CUtensorMapFloatOOBfill);

extern "C" void kernel_launch(void* const* d_in, const int* in_sizes, int n_in,
                              void* d_out, int out_size) {
    const float* inputs    = (const float*)d_in[0];
    const int*   targets   = (const int*)  d_in[1];
    const float* prototype = (const float*)d_in[2];
    const float* features  = (const float*)d_in[3];
    float* out = (float*)d_out;

    cudaFuncSetAttribute(k_gemm, cudaFuncAttributeMaxDynamicSharedMemorySize,
                         SMEM_DYN);

    PFN_tmapenc enc = nullptr;
    cudaDriverEntryPointQueryResult qr;
    cudaGetDriverEntryPointByVersion("cuTensorMapEncodeTiled", (void**)&enc,
                                     12000, cudaEnableDefault, &qr);

    void* xnbp = nullptr;
    cudaGetSymbolAddress(&xnbp, g_xnb);

    CUtensorMap tmA, tmB;
    {
        cuuint64_t dims[2]    = {Dd, Bb};
        cuuint64_t strides[1] = {Dd * 2ull};
        cuuint32_t box[2]     = {KC, Bb};          // 32 bf16 = 64 B x 256 rows
        cuuint32_t es[2]      = {1, 1};
        enc(&tmA, CU_TENSOR_MAP_DATA_TYPE_BFLOAT16, 2, xnbp, dims, strides, box, es,
            CU_TENSOR_MAP_INTERLEAVE_NONE, CU_TENSOR_MAP_SWIZZLE_64B,
            CU_TENSOR_MAP_L2_PROMOTION_L2_128B, CU_TENSOR_MAP_FLOAT_OOB_FILL_NONE);
    }
    {
        cuuint64_t dims[2]    = {Dd, Nn};
        cuuint64_t strides[1] = {Dd * 4ull};
        cuuint32_t box[2]     = {KC, BNg};         // 32 f32 = 128 B x 128 rows
        cuuint32_t es[2]      = {1, 1};
        enc(&tmB, CU_TENSOR_MAP_DATA_TYPE_FLOAT32, 2, (void*)features,
            dims, strides, box, es,
            CU_TENSOR_MAP_INTERLEAVE_NONE, CU_TENSOR_MAP_SWIZZLE_128B,
            CU_TENSOR_MAP_L2_PROMOTION_L2_128B, CU_TENSOR_MAP_FLOAT_OOB_FILL_NONE);
    }

    k_normalize<<<Bb, 256>>>(inputs);
    k_prep<<<Bb, 256>>>(prototype);
    k_target<<<Bb, 256>>>(features, targets);
    k_gemm<<<NBLK, 256, SMEM_DYN>>>(tmA, tmB);
    k_finalrow<<<Bb, 256>>>();
    k_final<<<1, 256>>>(out);
}

// round 12
// speedup vs baseline: 1.1041x; 1.0830x over previous
#include <cuda_runtime.h>
#include <cuda.h>
#include <cuda_bf16.h>
#include <math.h>
#include <stdint.h>

#define Bb 256
#define Dd 2048
#define Nn 65536
#define Pp 4096
#define CTOT (Pp + Nn)
#define TINV 20.0f
#define EPS_ 0.1f

#define BMg 128                  // M rows per CTA
#define BNg 128                  // N cols per CTA
#define NBLK (Nn / BNg)          // 512 N-blocks
#define KC 32                    // K elems per stage
#define NIT (Dd / KC)            // 64 stages
#define NSTG 3
#define A_BY 8192                // A bf16: 128 rows x 64 B (SW64)
#define BF_BY 16384              // B fp32: 128 rows x 128 B (SW128)
#define BB_BY 8192               // B bf16: 128 rows x 64 B (SW64-style)
#define STG_BY (A_BY + BF_BY + BB_BY)   // 32768
#define SMEM_DYN (NSTG * STG_BY + 1024) // 99328

__device__ __align__(128) float g_xn[Bb * Dd];
__device__ __align__(128) __nv_bfloat16 g_xnb[Bb * Dd];
__device__ float g_M[Bb], g_szp[Bb], g_sep[Bb], g_zt[Bb], g_rowloss[Bb];
__device__ float g_psv[Bb * NBLK], g_pse[Bb * NBLK];

// ---------------- PTX helpers ----------------
__device__ __forceinline__ uint32_t cvs(const void* p) {
    return (uint32_t)__cvta_generic_to_shared(p);
}
__device__ __forceinline__ void mbar_init(uint32_t a, uint32_t c) {
    asm volatile("mbarrier.init.shared.b64 [%0], %1;" :: "r"(a), "r"(c) : "memory");
}
__device__ __forceinline__ void mbar_expect(uint32_t a, uint32_t tx) {
    asm volatile("mbarrier.arrive.expect_tx.shared.b64 _, [%0], %1;"
                 :: "r"(a), "r"(tx) : "memory");
}
__device__ __forceinline__ void mbar_wait(uint32_t a, uint32_t ph) {
    asm volatile(
        "{\n\t.reg .pred P;\n\t"
        "W_%=:\n\t"
        "mbarrier.try_wait.parity.acquire.cta.shared::cta.b64 P, [%0], %1, 0x989680;\n\t"
        "@P bra D_%=;\n\t"
        "bra.uni W_%=;\n\t"
        "D_%=:\n\t}"
        :: "r"(a), "r"(ph) : "memory");
}
__device__ __forceinline__ void tma2d(uint32_t dst, const CUtensorMap* m,
                                      int x, int y, uint32_t bar) {
    asm volatile(
        "cp.async.bulk.tensor.2d.shared::cta.global.tile.mbarrier::complete_tx::bytes "
        "[%0], [%1, {%2, %3}], [%4];"
        :: "r"(dst), "l"(m), "r"(x), "r"(y), "r"(bar) : "memory");
}
__device__ __forceinline__ void ldsm4(uint32_t& r0, uint32_t& r1, uint32_t& r2,
                                      uint32_t& r3, uint32_t addr) {
    asm volatile(
        "ldmatrix.sync.aligned.m8n8.x4.shared.b16 {%0,%1,%2,%3}, [%4];"
        : "=r"(r0), "=r"(r1), "=r"(r2), "=r"(r3) : "r"(addr));
}
__device__ __forceinline__ void mma16(float c[4], const uint32_t a[4],
                                      uint32_t b0, uint32_t b1) {
    asm("mma.sync.aligned.m16n8k16.row.col.f32.bf16.bf16.f32 "
        "{%0,%1,%2,%3},{%4,%5,%6,%7},{%8,%9},{%0,%1,%2,%3};"
        : "+f"(c[0]), "+f"(c[1]), "+f"(c[2]), "+f"(c[3])
        : "r"(a[0]), "r"(a[1]), "r"(a[2]), "r"(a[3]), "r"(b0), "r"(b1));
}
__device__ __forceinline__ uint32_t pack2(float a, float b) {
    __nv_bfloat162 p = __floats2bfloat162_rn(a, b);
    return *(uint32_t*)&p;
}

// ---------------- K1: normalize inputs (fp32 + bf16 out) ----------------
__global__ void k_normalize(const float* __restrict__ in) {
    int row = blockIdx.x, tid = threadIdx.x;
    const float4* src = (const float4*)(in + (size_t)row * Dd);
    float4 v0 = src[tid], v1 = src[tid + 256];
    float ss = v0.x*v0.x + v0.y*v0.y + v0.z*v0.z + v0.w*v0.w
             + v1.x*v1.x + v1.y*v1.y + v1.z*v1.z + v1.w*v1.w;
    #pragma unroll
    for (int o = 16; o; o >>= 1) ss += __shfl_xor_sync(~0u, ss, o);
    __shared__ float sh[8];
    if ((tid & 31) == 0) sh[tid >> 5] = ss;
    __syncthreads();
    if (tid == 0) {
        float t = 0.f;
        #pragma unroll
        for (int i = 0; i < 8; i++) t += sh[i];
        sh[0] = rsqrtf(t);
    }
    __syncthreads();
    float iv = sh[0];
    v0.x*=iv; v0.y*=iv; v0.z*=iv; v0.w*=iv;
    v1.x*=iv; v1.y*=iv; v1.z*=iv; v1.w*=iv;
    float4* dst = (float4*)(g_xn + (size_t)row * Dd);
    dst[tid] = v0; dst[tid + 256] = v1;
    uint2* bdst = (uint2*)(g_xnb + (size_t)row * Dd);
    bdst[tid]       = make_uint2(pack2(v0.x, v0.y), pack2(v0.z, v0.w));
    bdst[tid + 256] = make_uint2(pack2(v1.x, v1.y), pack2(v1.z, v1.w));
}

// ---------------- K2: prototype stats ----------------
__global__ void k_prep(const float* __restrict__ proto) {
    int b = blockIdx.x, tid = threadIdx.x;
    const float4* pr = (const float4*)(proto + (size_t)b * Pp);
    float mx = -1e30f, sm = 0.f;
    #pragma unroll 4
    for (int i = tid; i < Pp / 4; i += 256) {
        float4 v = pr[i];
        sm += (v.x + v.y) + (v.z + v.w);
        mx = fmaxf(fmaxf(fmaxf(v.x, v.y), fmaxf(v.z, v.w)), mx);
    }
    __shared__ float rm[256], rs[256];
    rm[tid] = mx; rs[tid] = sm;
    __syncthreads();
    for (int o = 128; o; o >>= 1) {
        if (tid < o) { rm[tid] = fmaxf(rm[tid], rm[tid+o]); rs[tid] += rs[tid+o]; }
        __syncthreads();
    }
    float M = fmaxf(rm[0] * TINV, 21.f), S = rs[0] * TINV;
    __syncthreads();
    float se = 0.f;
    for (int i = tid; i < Pp / 4; i += 256) {
        float4 v = pr[i];
        if (fmaxf(fmaxf(v.x, v.y), fmaxf(v.z, v.w)) * TINV > M - 30.f) {
            se += __expf(v.x*TINV - M) + __expf(v.y*TINV - M)
                + __expf(v.z*TINV - M) + __expf(v.w*TINV - M);
        }
    }
    rs[tid] = se;
    __syncthreads();
    for (int o = 128; o; o >>= 1) {
        if (tid < o) rs[tid] += rs[tid+o];
        __syncthreads();
    }
    if (tid == 0) { g_M[b] = M; g_szp[b] = S; g_sep[b] = rs[0]; }
}

// ---------------- K3: exact fp32 target logit ----------------
__global__ void k_target(const float* __restrict__ F, const int* __restrict__ tg) {
    int b = blockIdx.x, tid = threadIdx.x;
    const float4* f = (const float4*)(F + (size_t)tg[b] * Dd);
    const float4* x = (const float4*)(g_xn + (size_t)b * Dd);
    float d = 0.f;
    for (int i = tid; i < Dd / 4; i += 256) {
        float4 a = x[i], c = f[i];
        d += a.x*c.x + a.y*c.y + a.z*c.z + a.w*c.w;
    }
    #pragma unroll
    for (int o = 16; o; o >>= 1) d += __shfl_xor_sync(~0u, d, o);
    __shared__ float sh[8];
    if ((tid & 31) == 0) sh[tid >> 5] = d;
    __syncthreads();
    if (tid == 0) {
        float t = 0.f;
        #pragma unroll
        for (int i = 0; i < 8; i++) t += sh[i];
        g_zt[b] = t * TINV;
    }
}

// ---------------- K4: 2-CTA/SM TMA + ldmatrix bf16 GEMM ----------
// CTA tile 128(M) x 128(N), stage k=32, 3 slots; 128 threads, 4 warps 2mx2n,
// warp tile 64x64. Grid (2, 512): M-half fastest -> the 2 CTAs sharing a
// B-tile are bid-adjacent (same wave, B reuse hits L2). Two CTAs per SM
// overlap each other's barrier/convert bubbles.
__global__ void __launch_bounds__(128, 2) k_gemm(
    const __grid_constant__ CUtensorMap tmA,
    const __grid_constant__ CUtensorMap tmB) {
    extern __shared__ char dsm[];
    __shared__ __align__(8) uint64_t s_bar[NSTG];   // full[0..2]

    int tid = threadIdx.x, lane = tid & 31, wid = tid >> 5;
    int wm = wid >> 1, wn = wid & 1;
    int m0 = blockIdx.x * BMg;
    int n0 = blockIdx.y * BNg;
    uint32_t sb = (cvs(dsm) + 1023u) & ~1023u;
    uint32_t fullb = cvs(s_bar);

    if (tid == 0) {
        #pragma unroll
        for (int i = 0; i < NSTG; i++) mbar_init(fullb + 8*i, 1);
    }
    __syncthreads();
    if (tid == 0) {
        #pragma unroll
        for (int p = 0; p < NSTG; p++) {
            mbar_expect(fullb + 8*p, A_BY + BF_BY);
            tma2d(sb + p*STG_BY,        &tmA, p*KC, m0, fullb + 8*p);
            tma2d(sb + p*STG_BY + A_BY, &tmB, p*KC, n0, fullb + 8*p);
        }
    }

    // ---- conversion geometry: 1 thread per B row, 32 floats each ----
    int cn = tid;
    uint32_t Xc  = (uint32_t)(cn & 7) << 4;          // SW128 (fp32 src)
    uint32_t Xc6 = (uint32_t)((cn >> 1) & 3) << 4;   // SW64 (bf16 dst)
    uint32_t csrc = (uint32_t)(A_BY + cn * 128);
    uint32_t cdst = (uint32_t)(A_BY + BF_BY + cn * 64);

    // ---- ldmatrix lane geometry (64-B rows, SW64: X=((r>>1)&3)<<4) ----
    int l15 = lane & 15;
    uint32_t aHi = (uint32_t)(lane >> 4) << 4;
    uint32_t rowAddrA[4], Xa[4];
    #pragma unroll
    for (int mt = 0; mt < 4; mt++) {
        int row = wm*64 + mt*16 + l15;
        rowAddrA[mt] = (uint32_t)row * 64u;
        Xa[mt] = (uint32_t)((row >> 1) & 3) << 4;
    }
    int j = lane >> 3;
    uint32_t bCol = (uint32_t)(j & 1) << 4;
    uint32_t rowAddrB[4], Xb[4];
    #pragma unroll
    for (int u = 0; u < 4; u++) {
        int row = wn*64 + u*16 + (lane & 7) + (j >> 1) * 8;
        rowAddrB[u] = (uint32_t)(A_BY + BF_BY) + (uint32_t)row * 64u;
        Xb[u] = (uint32_t)((row >> 1) & 3) << 4;
    }

    float c[4][8][4];
    #pragma unroll
    for (int i = 0; i < 4; i++)
        #pragma unroll
        for (int jj = 0; jj < 8; jj++)
            #pragma unroll
            for (int k = 0; k < 4; k++) c[i][jj][k] = 0.f;

    // convert stage stg's B fp32 -> bf16 (this thread's 32 floats)
    auto do_convert = [&](int stg) {
        uint32_t base = sb + (uint32_t)(stg % NSTG) * STG_BY;
        uint32_t srcb = base + csrc;
        uint32_t dstb = base + cdst;
        #pragma unroll
        for (int h = 0; h < 2; h++) {
            uint32_t so = (uint32_t)h * 64u;
            uint32_t dofs = (uint32_t)h * 32u;
            float4 f0, f1, f2, f3;
            asm volatile("ld.shared.v4.f32 {%0,%1,%2,%3}, [%4];"
                : "=f"(f0.x), "=f"(f0.y), "=f"(f0.z), "=f"(f0.w)
                : "r"(srcb + ((so +  0u) ^ Xc)));
            asm volatile("ld.shared.v4.f32 {%0,%1,%2,%3}, [%4];"
                : "=f"(f1.x), "=f"(f1.y), "=f"(f1.z), "=f"(f1.w)
                : "r"(srcb + ((so + 16u) ^ Xc)));
            asm volatile("ld.shared.v4.f32 {%0,%1,%2,%3}, [%4];"
                : "=f"(f2.x), "=f"(f2.y), "=f"(f2.z), "=f"(f2.w)
                : "r"(srcb + ((so + 32u) ^ Xc)));
            asm volatile("ld.shared.v4.f32 {%0,%1,%2,%3}, [%4];"
                : "=f"(f3.x), "=f"(f3.y), "=f"(f3.z), "=f"(f3.w)
                : "r"(srcb + ((so + 48u) ^ Xc)));
            asm volatile("st.shared.v4.b32 [%0], {%1,%2,%3,%4};"
                :: "r"(dstb + ((dofs +  0u) ^ Xc6)),
                   "r"(pack2(f0.x, f0.y)), "r"(pack2(f0.z, f0.w)),
                   "r"(pack2(f1.x, f1.y)), "r"(pack2(f1.z, f1.w)) : "memory");
            asm volatile("st.shared.v4.b32 [%0], {%1,%2,%3,%4};"
                :: "r"(dstb + ((dofs + 16u) ^ Xc6)),
                   "r"(pack2(f2.x, f2.y)), "r"(pack2(f2.z, f2.w)),
                   "r"(pack2(f3.x, f3.y)), "r"(pack2(f3.z, f3.w)) : "memory");
        }
    };

    // compute stage resident in slot sbase
    auto do_compute = [&](uint32_t sbase) {
        #pragma unroll
        for (int s4 = 0; s4 < 2; s4++) {
            uint32_t kb = (uint32_t)s4 * 32u;
            uint32_t a[4][4], bfr[4][4];
            #pragma unroll
            for (int mt = 0; mt < 4; mt++)
                ldsm4(a[mt][0], a[mt][1], a[mt][2], a[mt][3],
                      sbase + rowAddrA[mt] + ((kb + aHi) ^ Xa[mt]));
            #pragma unroll
            for (int u = 0; u < 4; u++)
                ldsm4(bfr[u][0], bfr[u][1], bfr[u][2], bfr[u][3],
                      sbase + rowAddrB[u] + ((kb + bCol) ^ Xb[u]));
            #pragma unroll
            for (int mt = 0; mt < 4; mt++)
                #pragma unroll
                for (int u = 0; u < 4; u++) {
                    mma16(c[mt][2*u],     a[mt], bfr[u][0], bfr[u][1]);
                    mma16(c[mt][2*u + 1], a[mt], bfr[u][2], bfr[u][3]);
                }
        }
    };

    // ---- prologue: wait stage 0, convert it, sync ----
    mbar_wait(fullb + 0, 0);
    do_convert(0);
    __syncthreads();

    for (int it = 0; it < NIT; it++) {
        int s = it % NSTG;
        uint32_t sbase = sb + (uint32_t)s * STG_BY;

        do_compute(sbase);

        if (it + 1 < NIT) {
            int st = it + 1;
            mbar_wait(fullb + 8*(st % NSTG), (uint32_t)((st / NSTG) & 1));
            do_convert(st);
        }

        // single barrier: compute(s) reads done + convert(it+1) writes visible
        __syncthreads();

        // refill slot s with stage it+3
        if (tid == 0 && it + NSTG < NIT) {
            int k0 = (it + NSTG) * KC;
            mbar_expect(fullb + 8*s, A_BY + BF_BY);
            tma2d(sbase,        &tmA, k0, m0, fullb + 8*s);
            tma2d(sbase + A_BY, &tmB, k0, n0, fullb + 8*s);
        }
    }
    __syncthreads();

    // ---- fused epilogue: per-row sum + softmax numerator partials ----
    int g = lane >> 2, q = lane & 3;
    float* redv = (float*)dsm;          // [2 wn][128 rows]
    float* rede = redv + 256;
    #pragma unroll
    for (int mt = 0; mt < 4; mt++) {
        int r0 = wm*64 + mt*16 + g;
        float M0 = g_M[m0 + r0], M1 = g_M[m0 + r0 + 8];
        float sv0 = 0.f, se0 = 0.f, sv1 = 0.f, se1 = 0.f;
        #pragma unroll
        for (int nt = 0; nt < 8; nt++) {
            float v;
            v = c[mt][nt][0]; sv0 += v; se0 += __expf(fmaf(TINV, v, -M0));
            v = c[mt][nt][1]; sv0 += v; se0 += __expf(fmaf(TINV, v, -M0));
            v = c[mt][nt][2]; sv1 += v; se1 += __expf(fmaf(TINV, v, -M1));
            v = c[mt][nt][3]; sv1 += v; se1 += __expf(fmaf(TINV, v, -M1));
        }
        #pragma unroll
        for (int o = 1; o <= 2; o <<= 1) {
            sv0 += __shfl_xor_sync(~0u, sv0, o);
            se0 += __shfl_xor_sync(~0u, se0, o);
            sv1 += __shfl_xor_sync(~0u, sv1, o);
            se1 += __shfl_xor_sync(~0u, se1, o);
        }
        if (q == 0) {
            redv[wn*128 + r0]     = sv0; rede[wn*128 + r0]     = se0;
            redv[wn*128 + r0 + 8] = sv1; rede[wn*128 + r0 + 8] = se1;
        }
    }
    __syncthreads();
    {
        float sv = redv[tid] + redv[128 + tid];
        float se = rede[tid] + rede[128 + tid];
        g_psv[(size_t)(m0 + tid) * NBLK + blockIdx.y] = sv;
        g_pse[(size_t)(m0 + tid) * NBLK + blockIdx.y] = se;
    }
}

// ---------------- K5: per-row combine over 512 N-block partials ------------
__global__ void k_finalrow(void) {
    int b = blockIdx.x, tid = threadIdx.x;
    float sv = g_psv[(size_t)b * NBLK + tid] + g_psv[(size_t)b * NBLK + tid + 256];
    float se = g_pse[(size_t)b * NBLK + tid] + g_pse[(size_t)b * NBLK + tid + 256];
    __shared__ float rv[256], re[256];
    rv[tid] = sv; re[tid] = se;
    __syncthreads();
    for (int o = 128; o; o >>= 1) {
        if (tid < o) { rv[tid] += rv[tid+o]; re[tid] += re[tid+o]; }
        __syncthreads();
    }
    if (tid == 0) {
        float M = g_M[b];
        float lse = M + logf(g_sep[b] + re[0]);
        float T = g_szp[b] + TINV * rv[0];
        g_rowloss[b] = lse - (1.f - EPS_) * g_zt[b] - EPS_ * (T / (float)CTOT);
    }
}

// ---------------- K6: mean ----------------
__global__ void k_final(float* __restrict__ out) {
    int tid = threadIdx.x;
    float v = g_rowloss[tid];
    #pragma unroll
    for (int o = 16; o; o >>= 1) v += __shfl_xor_sync(~0u, v, o);
    __shared__ float sh[8];
    if ((tid & 31) == 0) sh[tid >> 5] = v;
    __syncthreads();
    if (tid == 0) {
        float s = 0.f;
        #pragma unroll
        for (int i = 0; i < 8; i++) s += sh[i];
        out[0] = s / (float)Bb;
    }
}

// ---------------------------------------------------------------------------
typedef CUresult (*PFN_tmapenc)(
    CUtensorMap*, CUtensorMapDataType, cuuint32_t, void*,
    const cuuint64_t*, const cuuint64_t*, const cuuint32_t*, const cuuint32_t*,
    CUtensorMapInterleave, CUtensorMapSwizzle, CUtensorMapL2promotion,
    CUtensorMapFloatOOBfill);

extern "C" void kernel_launch(void* const* d_in, const int* in_sizes, int n_in,
                              void* d_out, int out_size) {
    const float* inputs    = (const float*)d_in[0];
    const int*   targets   = (const int*)  d_in[1];
    const float* prototype = (const float*)d_in[2];
    const float* features  = (const float*)d_in[3];
    float* out = (float*)d_out;

    cudaFuncSetAttribute(k_gemm, cudaFuncAttributeMaxDynamicSharedMemorySize,
                         SMEM_DYN);

    PFN_tmapenc enc = nullptr;
    cudaDriverEntryPointQueryResult qr;
    cudaGetDriverEntryPointByVersion("cuTensorMapEncodeTiled", (void**)&enc,
                                     12000, cudaEnableDefault, &qr);

    void* xnbp = nullptr;
    cudaGetSymbolAddress(&xnbp, g_xnb);

    CUtensorMap tmA, tmB;
    {
        cuuint64_t dims[2]    = {Dd, Bb};
        cuuint64_t strides[1] = {Dd * 2ull};
        cuuint32_t box[2]     = {KC, BMg};         // 32 bf16 = 64 B x 128 rows
        cuuint32_t es[2]      = {1, 1};
        enc(&tmA, CU_TENSOR_MAP_DATA_TYPE_BFLOAT16, 2, xnbp, dims, strides, box, es,
            CU_TENSOR_MAP_INTERLEAVE_NONE, CU_TENSOR_MAP_SWIZZLE_64B,
            CU_TENSOR_MAP_L2_PROMOTION_L2_128B, CU_TENSOR_MAP_FLOAT_OOB_FILL_NONE);
    }
    {
        cuuint64_t dims[2]    = {Dd, Nn};
        cuuint64_t strides[1] = {Dd * 4ull};
        cuuint32_t box[2]     = {KC, BNg};         // 32 f32 = 128 B x 128 rows
        cuuint32_t es[2]      = {1, 1};
        enc(&tmB, CU_TENSOR_MAP_DATA_TYPE_FLOAT32, 2, (void*)features,
            dims, strides, box, es,
            CU_TENSOR_MAP_INTERLEAVE_NONE, CU_TENSOR_MAP_SWIZZLE_128B,
            CU_TENSOR_MAP_L2_PROMOTION_L2_128B, CU_TENSOR_MAP_FLOAT_OOB_FILL_NONE);
    }

    k_normalize<<<Bb, 256>>>(inputs);
    k_prep<<<Bb, 256>>>(prototype);
    k_target<<<Bb, 256>>>(features, targets);
    dim3 grid(2, NBLK);
    k_gemm<<<grid, 128, SMEM_DYN>>>(tmA, tmB);
    k_finalrow<<<Bb, 256>>>();
    k_final<<<1, 256>>>(out);
}